// round 1
// baseline (speedup 1.0000x reference)
#include <cuda_runtime.h>
#include <cstddef>

#define BB 8
#define LL 2048
#define DM 1024
#define HH 120
#define HP 128
#define MTOT (BB*LL)
#define LOG2E 1.4426950408889634f

// Scratch (static __device__ arrays: allocation-free per harness rules)
__device__ float g_Wc[DM * HP];     // q_weight^T @ weight, padded to 128 cols
__device__ float g_bc[HP];          // q_bias @ weight, padded
__device__ float g_u[MTOT * HH];    // u = query @ Wc + bc   [16384][120]
__device__ float g_norm[MTOT];      // ||u_i||^2

// ---------------------------------------------------------------------------
// K1: Wc[d][h] = sum_p q_weight[p][d] * weight[p][h];  bc[h] = sum_p qb[p]*w[p][h]
// ---------------------------------------------------------------------------
__global__ void k_prep(const float* __restrict__ qw,
                       const float* __restrict__ qb,
                       const float* __restrict__ w) {
    int d = blockIdx.x;      // 0..1023
    int h = threadIdx.x;     // 0..127
    float acc = 0.f;
    if (h < HH) {
        #pragma unroll 4
        for (int p = 0; p < HH; ++p)
            acc += qw[p * DM + d] * w[p * HH + h];
    }
    g_Wc[d * HP + h] = acc;
    if (d == 0) {
        float b = 0.f;
        if (h < HH) {
            #pragma unroll 4
            for (int p = 0; p < HH; ++p)
                b += qb[p] * w[p * HH + h];
        }
        g_bc[h] = b;
    }
}

// ---------------------------------------------------------------------------
// K2: u = query @ Wc + bc, plus norms.  M=16384, N=128(120 live), K=1024.
// CTA tile 128x128, 256 threads, 8x8 register tiles, BK=16.
// ---------------------------------------------------------------------------
__global__ __launch_bounds__(256) void k_proj(const float* __restrict__ q) {
    __shared__ float Qs[16][132];   // transposed: Qs[k][m]
    __shared__ float Ws[16][128];   // natural:    Ws[k][n]

    int tid = threadIdx.x;
    int ty = tid >> 4;              // row group 0..15
    int tx = tid & 15;              // col group 0..15
    int m0 = blockIdx.x * 128;

    float acc[8][8];
    #pragma unroll
    for (int r = 0; r < 8; ++r)
        #pragma unroll
        for (int c = 0; c < 8; ++c) acc[r][c] = 0.f;

    for (int kb = 0; kb < DM; kb += 16) {
        // Q tile: 128 rows x 16 k  (512 float4, 2 per thread), store transposed
        #pragma unroll
        for (int l = 0; l < 2; ++l) {
            int id = tid + 256 * l;
            int row = id >> 2;
            int k4 = (id & 3) * 4;
            float4 v = *(const float4*)&q[(size_t)(m0 + row) * DM + kb + k4];
            Qs[k4 + 0][row] = v.x;
            Qs[k4 + 1][row] = v.y;
            Qs[k4 + 2][row] = v.z;
            Qs[k4 + 3][row] = v.w;
        }
        // Wc tile: 16 k x 128 n  (512 float4, 2 per thread), natural layout
        #pragma unroll
        for (int l = 0; l < 2; ++l) {
            int id = tid + 256 * l;
            int kk = id >> 5;
            int c4 = (id & 31) * 4;
            *(float4*)&Ws[kk][c4] = *(const float4*)&g_Wc[(kb + kk) * HP + c4];
        }
        __syncthreads();

        #pragma unroll 4
        for (int k = 0; k < 16; ++k) {
            float a[8], bvec[8];
            *(float4*)&a[0]    = *(const float4*)&Qs[k][ty * 8];
            *(float4*)&a[4]    = *(const float4*)&Qs[k][ty * 8 + 4];
            *(float4*)&bvec[0] = *(const float4*)&Ws[k][tx * 8];
            *(float4*)&bvec[4] = *(const float4*)&Ws[k][tx * 8 + 4];
            #pragma unroll
            for (int r = 0; r < 8; ++r)
                #pragma unroll
                for (int c = 0; c < 8; ++c)
                    acc[r][c] += a[r] * bvec[c];
        }
        __syncthreads();
    }

    // Epilogue: add bias, write u, accumulate row partial of ||u||^2
    float bcw[8];
    #pragma unroll
    for (int c = 0; c < 8; ++c) bcw[c] = g_bc[tx * 8 + c];

    float part[8];
    #pragma unroll
    for (int r = 0; r < 8; ++r) {
        float uv[8];
        #pragma unroll
        for (int c = 0; c < 8; ++c) uv[c] = acc[r][c] + bcw[c];
        if (tx < 15) {  // cols 0..119 only
            int row = m0 + ty * 8 + r;
            *(float4*)&g_u[(size_t)row * HH + tx * 8]     = make_float4(uv[0], uv[1], uv[2], uv[3]);
            *(float4*)&g_u[(size_t)row * HH + tx * 8 + 4] = make_float4(uv[4], uv[5], uv[6], uv[7]);
            float s = 0.f;
            #pragma unroll
            for (int c = 0; c < 8; ++c) s += uv[c] * uv[c];
            part[r] = s;
        } else {
            part[r] = 0.f;
        }
    }

    // Reduce partials across the 16 col-groups (reuse Qs: 2112 floats >= 2048)
    __syncthreads();
    float* red = &Qs[0][0];
    #pragma unroll
    for (int r = 0; r < 8; ++r) red[tx * 128 + ty * 8 + r] = part[r];
    __syncthreads();
    if (tid < 128) {
        float s = 0.f;
        #pragma unroll
        for (int t = 0; t < 16; ++t) s += red[t * 128 + tid];
        g_norm[m0 + tid] = s;
    }
}

// ---------------------------------------------------------------------------
// K3: per (batch, 128-row stripe): S = u_i . u_j over all 2048 cols, fused
// d = ni + nj - 2*S;  s = exp(-0.5*scale*d);  e = exp(s);  softmax normalize.
// Each CTA owns a full row stripe -> exact row sums, no atomics, then an
// in-kernel second pass divides its own just-written (L2-hot) outputs.
// ---------------------------------------------------------------------------
extern __shared__ float sm3[];
__global__ __launch_bounds__(256) void k_attn(const float* __restrict__ pid,
                                              float* __restrict__ out) {
    float* As = sm3;                 // [120][132] transposed u_i stripe
    float* Bs = sm3 + 120 * 132;     // [120][132] transposed u_j tile

    int tid = threadIdx.x;
    int ty = tid >> 4;
    int tx = tid & 15;
    int b = blockIdx.y;
    int stripe = blockIdx.x;
    int i0 = b * LL + stripe * 128;       // global row base into g_u / g_norm

    float scale = pid[0] * pid[0];
    float c1 = -0.5f * scale * LOG2E;

    // Load A stripe (128 rows x 120 k), transposed. 3840 float4, 15/thread.
    #pragma unroll
    for (int l = 0; l < 15; ++l) {
        int id = tid + 256 * l;
        int row = id / 30;
        int k4 = (id % 30) * 4;
        float4 v = *(const float4*)&g_u[(size_t)(i0 + row) * HH + k4];
        As[(k4 + 0) * 132 + row] = v.x;
        As[(k4 + 1) * 132 + row] = v.y;
        As[(k4 + 2) * 132 + row] = v.z;
        As[(k4 + 3) * 132 + row] = v.w;
    }

    float nir[8];
    #pragma unroll
    for (int r = 0; r < 8; ++r) nir[r] = g_norm[i0 + ty * 8 + r];

    float rsum[8];
    #pragma unroll
    for (int r = 0; r < 8; ++r) rsum[r] = 0.f;

    int iRowBase = stripe * 128 + ty * 8;

    for (int jt = 0; jt < 16; ++jt) {
        int j0 = b * LL + jt * 128;
        __syncthreads();  // prior compute done before overwriting Bs (also fences As stores on jt=0)
        #pragma unroll
        for (int l = 0; l < 15; ++l) {
            int id = tid + 256 * l;
            int row = id / 30;
            int k4 = (id % 30) * 4;
            float4 v = *(const float4*)&g_u[(size_t)(j0 + row) * HH + k4];
            Bs[(k4 + 0) * 132 + row] = v.x;
            Bs[(k4 + 1) * 132 + row] = v.y;
            Bs[(k4 + 2) * 132 + row] = v.z;
            Bs[(k4 + 3) * 132 + row] = v.w;
        }
        __syncthreads();

        float acc[8][8];
        #pragma unroll
        for (int r = 0; r < 8; ++r)
            #pragma unroll
            for (int c = 0; c < 8; ++c) acc[r][c] = 0.f;

        #pragma unroll 4
        for (int k = 0; k < HH; ++k) {
            float a[8], bvec[8];
            *(float4*)&a[0]    = *(const float4*)&As[k * 132 + ty * 8];
            *(float4*)&a[4]    = *(const float4*)&As[k * 132 + ty * 8 + 4];
            *(float4*)&bvec[0] = *(const float4*)&Bs[k * 132 + tx * 8];
            *(float4*)&bvec[4] = *(const float4*)&Bs[k * 132 + tx * 8 + 4];
            #pragma unroll
            for (int r = 0; r < 8; ++r)
                #pragma unroll
                for (int c = 0; c < 8; ++c)
                    acc[r][c] += a[r] * bvec[c];
        }

        // Epilogue: RBF kernel + exp, accumulate row sums, store unnormalized
        float njc[8];
        #pragma unroll
        for (int c = 0; c < 8; ++c) njc[c] = __ldg(&g_norm[j0 + tx * 8 + c]);

        #pragma unroll
        for (int r = 0; r < 8; ++r) {
            float ev[8];
            #pragma unroll
            for (int c = 0; c < 8; ++c) {
                float d = nir[r] + njc[c] - 2.f * acc[r][c];
                float s = exp2f(c1 * d);           // exp(-0.5*scale*d)
                float e = exp2f(LOG2E * s);        // exp(s)
                ev[c] = e;
                rsum[r] += e;
            }
            size_t o = ((size_t)b * LL + iRowBase + r) * LL + jt * 128 + tx * 8;
            *(float4*)&out[o]     = make_float4(ev[0], ev[1], ev[2], ev[3]);
            *(float4*)&out[o + 4] = make_float4(ev[4], ev[5], ev[6], ev[7]);
        }
    }

    // Reduce row sums across the 16 col-groups (reuse As region)
    __syncthreads();
    float* red = As;
    #pragma unroll
    for (int r = 0; r < 8; ++r) red[tx * 128 + ty * 8 + r] = rsum[r];
    __syncthreads();
    float* rinv = As + 2048;
    if (tid < 128) {
        float s = 0.f;
        #pragma unroll
        for (int t = 0; t < 16; ++t) s += red[t * 128 + tid];
        rinv[tid] = 1.0f / s;
    }
    __syncthreads();

    float rr[8];
    #pragma unroll
    for (int r = 0; r < 8; ++r) rr[r] = rinv[ty * 8 + r];

    // Normalize pass: each thread re-reads exactly its own writes (coherent)
    for (int jt = 0; jt < 16; ++jt) {
        #pragma unroll
        for (int r = 0; r < 8; ++r) {
            size_t o = ((size_t)b * LL + iRowBase + r) * LL + jt * 128 + tx * 8;
            float4 v0 = *(float4*)&out[o];
            float4 v1 = *(float4*)&out[o + 4];
            v0.x *= rr[r]; v0.y *= rr[r]; v0.z *= rr[r]; v0.w *= rr[r];
            v1.x *= rr[r]; v1.y *= rr[r]; v1.z *= rr[r]; v1.w *= rr[r];
            *(float4*)&out[o]     = v0;
            *(float4*)&out[o + 4] = v1;
        }
    }
}

// ---------------------------------------------------------------------------
extern "C" void kernel_launch(void* const* d_in, const int* in_sizes, int n_in,
                              void* d_out, int out_size) {
    const float* query = (const float*)d_in[0];
    // d_in[1] = key: unused by the reference module
    const float* q_weight = (const float*)d_in[2];
    const float* q_bias = (const float*)d_in[3];
    const float* weight = (const float*)d_in[4];
    const float* pid = (const float*)d_in[5];
    float* out = (float*)d_out;

    k_prep<<<DM, 128>>>(q_weight, q_bias, weight);
    k_proj<<<MTOT / 128, 256>>>(query);

    const int smem3 = 2 * 120 * 132 * (int)sizeof(float);  // 126720 B
    cudaFuncSetAttribute(k_attn, cudaFuncAttributeMaxDynamicSharedMemorySize, smem3);
    dim3 g3(LL / 128, BB);  // (16, 8) = 128 CTAs, one wave
    k_attn<<<g3, 256, smem3>>>(pid, out);
}

// round 6
// speedup vs baseline: 1.8333x; 1.8333x over previous
#include <cuda_runtime.h>
#include <cuda_bf16.h>
#include <cstdint>
#include <cstddef>

#define BB 8
#define LL 2048
#define DM 1024
#define HH 120
#define HP 128
#define MTOT (BB*LL)
#define LOG2E 1.4426950408889634f

// ---------------------------------------------------------------------------
// Scratch (__device__ globals: allocation-free per harness rules)
// ---------------------------------------------------------------------------
__device__ __align__(16) float g_bc[HP];                       // q_bias @ weight
__device__ __align__(16) float g_norm[MTOT];                   // ||u_i||^2 (fp32)
__device__ __align__(16) __nv_bfloat16 g_WtH[HP * DM];         // (Wc^T) hi  [h][d]
__device__ __align__(16) __nv_bfloat16 g_WtL[HP * DM];         // (Wc^T) lo
__device__ __align__(16) __nv_bfloat16 g_uh[(size_t)MTOT * HP];// u hi  [row][128]
__device__ __align__(16) __nv_bfloat16 g_ul[(size_t)MTOT * HP];// u lo

// ---------------------------------------------------------------------------
// Helpers
// ---------------------------------------------------------------------------
__device__ __forceinline__ uint32_t smem_u32(const void* p) {
    uint32_t a;
    asm("{ .reg .u64 t; cvta.to.shared.u64 t, %1; cvt.u32.u64 %0, t; }" : "=r"(a) : "l"(p));
    return a;
}
__device__ __forceinline__ void ldsm4(uint32_t (&r)[4], uint32_t addr) {
    asm volatile("ldmatrix.sync.aligned.m8n8.x4.shared.b16 {%0,%1,%2,%3}, [%4];"
        : "=r"(r[0]), "=r"(r[1]), "=r"(r[2]), "=r"(r[3]) : "r"(addr));
}
__device__ __forceinline__ void hmma(float (&c)[4], const uint32_t (&a)[4],
                                     uint32_t b0, uint32_t b1) {
    asm volatile("mma.sync.aligned.m16n8k16.row.col.f32.bf16.bf16.f32 "
        "{%0,%1,%2,%3}, {%4,%5,%6,%7}, {%8,%9}, {%0,%1,%2,%3};"
        : "+f"(c[0]), "+f"(c[1]), "+f"(c[2]), "+f"(c[3])
        : "r"(a[0]), "r"(a[1]), "r"(a[2]), "r"(a[3]), "r"(b0), "r"(b1));
}
__device__ __forceinline__ void cpa16(uint32_t dst, const void* src) {
    asm volatile("cp.async.cg.shared.global [%0], [%1], 16;" :: "r"(dst), "l"(src));
}
#define CP_COMMIT() asm volatile("cp.async.commit_group;" ::: "memory")
#define CP_WAIT0()  asm volatile("cp.async.wait_group 0;" ::: "memory")

__device__ __forceinline__ float ex2(float x) {
    float r; asm("ex2.approx.ftz.f32 %0, %1;" : "=f"(r) : "f"(x)); return r;
}
__device__ __forceinline__ void split_store(__nv_bfloat16* H, __nv_bfloat16* L,
                                            size_t idx, float x, float y) {
    __nv_bfloat162 h = __floats2bfloat162_rn(x, y);
    float hx = __bfloat162float(h.x), hy = __bfloat162float(h.y);
    __nv_bfloat162 lo = __floats2bfloat162_rn(x - hx, y - hy);
    *(__nv_bfloat162*)(H + idx) = h;
    *(__nv_bfloat162*)(L + idx) = lo;
}

// TN mma over one k-chunk. A,B smem tiles row-major [rows][k], stride STRB bytes.
// Warp tile 32(m) x 64(n): warps 4(m) x 2(n). KS ksteps of k=16.
template<int STRB, int KS>
__device__ __forceinline__ void mma_chunk(uint32_t aBase, uint32_t bBase,
                                          float (&acc)[2][8][4],
                                          int lid, int m0w, int n0) {
    uint32_t aA = aBase + (uint32_t)(m0w + (lid & 15)) * STRB + (uint32_t)((lid >> 4) * 16);
    uint32_t bA = bBase + (uint32_t)(n0 + (lid & 7) + ((lid >> 4) & 1) * 8) * STRB
                + (uint32_t)(((lid >> 3) & 1) * 16);
    #pragma unroll
    for (int ks = 0; ks < KS; ++ks) {
        uint32_t kb = (uint32_t)ks * 32;   // 16 bf16 = 32B per kstep
        uint32_t afr[2][4];
        #pragma unroll
        for (int mt = 0; mt < 2; ++mt) ldsm4(afr[mt], aA + mt * 16 * STRB + kb);
        uint32_t bfr[4][4];
        #pragma unroll
        for (int g = 0; g < 4; ++g)    ldsm4(bfr[g], bA + g * 16 * STRB + kb);
        #pragma unroll
        for (int mt = 0; mt < 2; ++mt)
            #pragma unroll
            for (int nt = 0; nt < 8; ++nt)
                hmma(acc[mt][nt], afr[mt],
                     bfr[nt >> 1][(nt & 1) * 2], bfr[nt >> 1][(nt & 1) * 2 + 1]);
    }
}

// ---------------------------------------------------------------------------
// K1: Wc^T (bf16 hi/lo) from q_weight, weight.  Wc[d][h]=sum_p qw[p][d]w[p][h]
// ---------------------------------------------------------------------------
__global__ __launch_bounds__(256) void k_prep(const float* __restrict__ qw,
                                              const float* __restrict__ w) {
    __shared__ float Aq[8][64];
    __shared__ float Ww[8][128];
    int tid = threadIdx.x;
    int ty = tid >> 4, tx = tid & 15;
    int d0 = blockIdx.x * 64;

    float acc[4][8];
    #pragma unroll
    for (int r = 0; r < 4; ++r)
        #pragma unroll
        for (int c = 0; c < 8; ++c) acc[r][c] = 0.f;

    for (int kk = 0; kk < HH; kk += 8) {
        {
            int i = tid >> 5, j = (tid & 31) * 2;
            const float* s = &qw[(size_t)(kk + i) * DM + d0 + j];
            Aq[i][j] = s[0]; Aq[i][j + 1] = s[1];
        }
        {
            int i = tid >> 5, c = (tid & 31) * 4;
            #pragma unroll
            for (int q2 = 0; q2 < 4; ++q2) {
                int h = c + q2;
                Ww[i][h] = (h < HH) ? w[(size_t)(kk + i) * HH + h] : 0.f;
            }
        }
        __syncthreads();
        #pragma unroll
        for (int k = 0; k < 8; ++k) {
            float a[4], b[8];
            #pragma unroll
            for (int r = 0; r < 4; ++r) a[r] = Aq[k][ty * 4 + r];
            *(float4*)&b[0] = *(const float4*)&Ww[k][tx * 8];
            *(float4*)&b[4] = *(const float4*)&Ww[k][tx * 8 + 4];
            #pragma unroll
            for (int r = 0; r < 4; ++r)
                #pragma unroll
                for (int c = 0; c < 8; ++c) acc[r][c] += a[r] * b[c];
        }
        __syncthreads();
    }
    #pragma unroll
    for (int r = 0; r < 4; ++r)
        #pragma unroll
        for (int c = 0; c < 8; ++c) {
            int h = tx * 8 + c, d = d0 + ty * 4 + r;
            float v = acc[r][c];
            __nv_bfloat16 hb = __float2bfloat16(v);
            g_WtH[(size_t)h * DM + d] = hb;
            g_WtL[(size_t)h * DM + d] = __float2bfloat16(v - __bfloat162float(hb));
        }
}

__global__ void k_bias(const float* __restrict__ qb, const float* __restrict__ w) {
    int h = threadIdx.x;
    float b = 0.f;
    if (h < HH) {
        #pragma unroll 4
        for (int p = 0; p < HH; ++p) b += qb[p] * w[p * HH + h];
    }
    g_bc[h] = b;
}

// ---------------------------------------------------------------------------
// K2: u = query @ Wc + bc via bf16 split-3 HMMA. M=16384, N=128, K=1024.
// Emits g_uh/g_ul (bf16) + g_norm (fp32). 128 CTAs x 256 thr.
// ---------------------------------------------------------------------------
#define P_AH 0
#define P_AL 18432
#define P_BH 36864
#define P_BL 55296
#define P_BC 73728
#define P_RED 74240
#define P_TOTAL 75264
#define STR2 144

extern __shared__ char smem_dyn[];

__global__ __launch_bounds__(256, 1) void k_proj(const float* __restrict__ q) {
    char* sm = smem_dyn;
    uint32_t sb = smem_u32(sm);
    int tid = threadIdx.x;
    int wid = tid >> 5, lid = tid & 31;
    int m0w = (wid & 3) * 32;
    int n0 = (wid >> 2) * 64;
    int m0g = blockIdx.x * 128;

    float* bc_s = (float*)(sm + P_BC);
    float* red = (float*)(sm + P_RED);
    if (tid < 128) bc_s[tid] = g_bc[tid];

    float acc[2][8][4];
    #pragma unroll
    for (int mt = 0; mt < 2; ++mt)
        #pragma unroll
        for (int nt = 0; nt < 8; ++nt)
            #pragma unroll
            for (int i = 0; i < 4; ++i) acc[mt][nt][i] = 0.f;

    // prefetch A chunk 0 into regs
    float4 qr[8];
    #pragma unroll
    for (int l = 0; l < 8; ++l) {
        int i = tid + 256 * l, r = i >> 4, c4 = (i & 15) * 4;
        qr[l] = *(const float4*)&q[(size_t)(m0g + r) * DM + c4];
    }

    for (int kbi = 0; kbi < 16; ++kbi) {
        int kb = kbi * 64;
        // B chunk via cp.async: 128 rows x 64 k bf16 = 128 rows x 8 16B-segs
        #pragma unroll
        for (int l = 0; l < 4; ++l) {
            int i = tid + 256 * l, r = i >> 3, sg = i & 7;
            uint32_t doff = (uint32_t)r * STR2 + sg * 16;
            size_t soff = (size_t)r * (DM * 2) + (size_t)kb * 2 + sg * 16;
            cpa16(sb + P_BH + doff, (const char*)g_WtH + soff);
            cpa16(sb + P_BL + doff, (const char*)g_WtL + soff);
        }
        CP_COMMIT();
        // A chunk: convert regs -> smem hi/lo
        #pragma unroll
        for (int l = 0; l < 8; ++l) {
            int i = tid + 256 * l, r = i >> 4, c4 = (i & 15) * 4;
            float4 v = qr[l];
            __nv_bfloat162 h01 = __floats2bfloat162_rn(v.x, v.y);
            __nv_bfloat162 h23 = __floats2bfloat162_rn(v.z, v.w);
            __nv_bfloat162 l01 = __floats2bfloat162_rn(v.x - __bfloat162float(h01.x),
                                                       v.y - __bfloat162float(h01.y));
            __nv_bfloat162 l23 = __floats2bfloat162_rn(v.z - __bfloat162float(h23.x),
                                                       v.w - __bfloat162float(h23.y));
            char* d = sm + P_AH + r * STR2 + c4 * 2;
            ((__nv_bfloat162*)d)[0] = h01; ((__nv_bfloat162*)d)[1] = h23;
            char* d2 = sm + P_AL + r * STR2 + c4 * 2;
            ((__nv_bfloat162*)d2)[0] = l01; ((__nv_bfloat162*)d2)[1] = l23;
        }
        if (kbi < 15) {
            #pragma unroll
            for (int l = 0; l < 8; ++l) {
                int i = tid + 256 * l, r = i >> 4, c4 = (i & 15) * 4;
                qr[l] = *(const float4*)&q[(size_t)(m0g + r) * DM + kb + 64 + c4];
            }
        }
        CP_WAIT0();
        __syncthreads();
        mma_chunk<STR2, 4>(sb + P_AH, sb + P_BH, acc, lid, m0w, n0);
        mma_chunk<STR2, 4>(sb + P_AH, sb + P_BL, acc, lid, m0w, n0);
        mma_chunk<STR2, 4>(sb + P_AL, sb + P_BH, acc, lid, m0w, n0);
        __syncthreads();
    }

    // Epilogue: bias, norms, bf16 split store
    float sums[2][2] = {{0.f, 0.f}, {0.f, 0.f}};
    #pragma unroll
    for (int mt = 0; mt < 2; ++mt)
        #pragma unroll
        for (int nt = 0; nt < 8; ++nt) {
            int col = n0 + nt * 8 + (lid & 3) * 2;
            float b0 = bc_s[col], b1 = bc_s[col + 1];
            int r1 = m0w + mt * 16 + (lid >> 2);
            float u00 = acc[mt][nt][0] + b0, u01 = acc[mt][nt][1] + b1;
            float u10 = acc[mt][nt][2] + b0, u11 = acc[mt][nt][3] + b1;
            sums[mt][0] += u00 * u00 + u01 * u01;
            sums[mt][1] += u10 * u10 + u11 * u11;
            split_store(g_uh, g_ul, (size_t)(m0g + r1) * HP + col, u00, u01);
            split_store(g_uh, g_ul, (size_t)(m0g + r1 + 8) * HP + col, u10, u11);
        }
    #pragma unroll
    for (int mt = 0; mt < 2; ++mt)
        #pragma unroll
        for (int hf = 0; hf < 2; ++hf) {
            float s = sums[mt][hf];
            s += __shfl_xor_sync(0xFFFFFFFF, s, 1);
            s += __shfl_xor_sync(0xFFFFFFFF, s, 2);
            if ((lid & 3) == 0)
                red[(wid >> 2) * 128 + m0w + mt * 16 + (lid >> 2) + hf * 8] = s;
        }
    __syncthreads();
    if (tid < 128) g_norm[m0g + tid] = red[tid] + red[128 + tid];
}

// ---------------------------------------------------------------------------
// K3: scores. One CTA per (batch, 128-row stripe); j-loop over 16 tiles.
// S via bf16 split-3 HMMA; fused RBF+exp+rowsum; staged coalesced stores;
// in-kernel softmax normalize.
// ---------------------------------------------------------------------------
#define A_H    0
#define A_L    34816
#define B0_H   69632
#define B1_H   139264
#define S_NJ   208896
#define S_NI   217088
#define S_RED  217600
#define S_RINV 218112
#define S_TOT  218624
#define STR3   272
#define BTILE  34816

__device__ __forceinline__ void k3_cp_tile(uint32_t dstH, uint32_t dstL,
                                           int row0, int tid) {
    #pragma unroll
    for (int l = 0; l < 8; ++l) {
        int i = tid + 256 * l, r = i >> 4, c = i & 15;
        uint32_t doff = (uint32_t)r * STR3 + c * 16;
        size_t soff = (size_t)(row0 + r) * (HP * 2) + c * 16;
        cpa16(dstH + doff, (const char*)g_uh + soff);
        cpa16(dstL + doff, (const char*)g_ul + soff);
    }
}

__global__ __launch_bounds__(256, 1) void k_attn(const float* __restrict__ pid,
                                                 float* __restrict__ out) {
    char* sm = smem_dyn;
    uint32_t sb = smem_u32(sm);
    int tid = threadIdx.x;
    int wid = tid >> 5, lid = tid & 31;
    int m0w = (wid & 3) * 32;
    int n0 = (wid >> 2) * 64;

    int b = blockIdx.y;
    int stripe = blockIdx.x;
    int i0 = b * LL + stripe * 128;

    float scale = pid[0] * pid[0];
    float c1 = -0.5f * scale * LOG2E;

    float* nj_s = (float*)(sm + S_NJ);
    float* ni_s = (float*)(sm + S_NI);
    float* red = (float*)(sm + S_RED);
    float* rinv_s = (float*)(sm + S_RINV);

    {   // nj (2048) + ni (128)
        float4* njd = (float4*)nj_s;
        const float4* njs = (const float4*)&g_norm[b * LL];
        njd[tid] = njs[tid];
        njd[tid + 256] = njs[tid + 256];
        if (tid < 128) ni_s[tid] = g_norm[i0 + tid];
    }
    k3_cp_tile(sb + A_H, sb + A_L, i0, tid);
    k3_cp_tile(sb + B0_H, sb + B0_H + BTILE, b * LL, tid);
    CP_COMMIT();
    CP_WAIT0();
    __syncthreads();

    float rs[16];
    #pragma unroll
    for (int r = 0; r < 16; ++r) rs[r] = 0.f;

    for (int jt = 0; jt < 16; ++jt) {
        int buf = jt & 1;
        uint32_t bH = sb + (buf ? B1_H : B0_H);
        uint32_t bL = bH + BTILE;
        if (jt < 15) {
            uint32_t nH = sb + ((buf ^ 1) ? B1_H : B0_H);
            k3_cp_tile(nH, nH + BTILE, b * LL + (jt + 1) * 128, tid);
            CP_COMMIT();
        }

        float acc[2][8][4];
        #pragma unroll
        for (int mt = 0; mt < 2; ++mt)
            #pragma unroll
            for (int nt = 0; nt < 8; ++nt)
                #pragma unroll
                for (int i = 0; i < 4; ++i) acc[mt][nt][i] = 0.f;

        mma_chunk<STR3, 8>(sb + A_H, bH, acc, lid, m0w, n0);
        mma_chunk<STR3, 8>(sb + A_H, bL, acc, lid, m0w, n0);
        mma_chunk<STR3, 8>(sb + A_L, bH, acc, lid, m0w, n0);
        __syncthreads();   // all ldmatrix reads of B(buf) done

        // stage acc (fp32) into consumed B buffer: [128][132] floats
        float* stg = (float*)(sm + (buf ? B1_H : B0_H));
        #pragma unroll
        for (int mt = 0; mt < 2; ++mt)
            #pragma unroll
            for (int nt = 0; nt < 8; ++nt) {
                int row = m0w + mt * 16 + (lid >> 2);
                int col = n0 + nt * 8 + (lid & 3) * 2;
                *(float2*)&stg[row * 132 + col] = make_float2(acc[mt][nt][0], acc[mt][nt][1]);
                *(float2*)&stg[(row + 8) * 132 + col] = make_float2(acc[mt][nt][2], acc[mt][nt][3]);
            }
        __syncthreads();

        // epilogue: warp w owns rows w*16..+15; coalesced 512B/warp stores
        #pragma unroll
        for (int rr = 0; rr < 16; ++rr) {
            int row = wid * 16 + rr;
            float nir = ni_s[row];
            float4 S4 = *(float4*)&stg[row * 132 + lid * 4];
            float4 nj4 = *(const float4*)&nj_s[jt * 128 + lid * 4];
            float e0 = ex2(LOG2E * ex2(c1 * (nir + nj4.x - 2.f * S4.x)));
            float e1 = ex2(LOG2E * ex2(c1 * (nir + nj4.y - 2.f * S4.y)));
            float e2 = ex2(LOG2E * ex2(c1 * (nir + nj4.z - 2.f * S4.z)));
            float e3 = ex2(LOG2E * ex2(c1 * (nir + nj4.w - 2.f * S4.w)));
            float p = (e0 + e1) + (e2 + e3);
            p += __shfl_xor_sync(0xFFFFFFFF, p, 16);
            p += __shfl_xor_sync(0xFFFFFFFF, p, 8);
            p += __shfl_xor_sync(0xFFFFFFFF, p, 4);
            p += __shfl_xor_sync(0xFFFFFFFF, p, 2);
            p += __shfl_xor_sync(0xFFFFFFFF, p, 1);
            rs[rr] += p;
            size_t o = (size_t)(i0 + row) * LL + jt * 128 + lid * 4;
            *(float4*)&out[o] = make_float4(e0, e1, e2, e3);
        }
        CP_WAIT0();
        __syncthreads();
    }

    if (lid == 0) {
        #pragma unroll
        for (int rr = 0; rr < 16; ++rr) red[wid * 16 + rr] = rs[rr];
    }
    __syncthreads();
    if (tid < 128) rinv_s[tid] = 1.0f / red[tid];
    __syncthreads();

    // normalize pass (coalesced; rows are L2-warm)
    #pragma unroll 1
    for (int rr = 0; rr < 16; ++rr) {
        int row = wid * 16 + rr;
        float sc = rinv_s[row];
        float* rp = &out[(size_t)(i0 + row) * LL];
        #pragma unroll 4
        for (int seg = 0; seg < 16; ++seg) {
            int idx = seg * 128 + lid * 4;
            float4 v = *(float4*)&rp[idx];
            v.x *= sc; v.y *= sc; v.z *= sc; v.w *= sc;
            *(float4*)&rp[idx] = v;
        }
    }
}

// ---------------------------------------------------------------------------
extern "C" void kernel_launch(void* const* d_in, const int* in_sizes, int n_in,
                              void* d_out, int out_size) {
    const float* query    = (const float*)d_in[0];
    // d_in[1] = key: unused by the reference module
    const float* q_weight = (const float*)d_in[2];
    const float* q_bias   = (const float*)d_in[3];
    const float* weight   = (const float*)d_in[4];
    const float* pid      = (const float*)d_in[5];
    float* out = (float*)d_out;

    k_prep<<<16, 256>>>(q_weight, weight);
    k_bias<<<1, 128>>>(q_bias, weight);

    cudaFuncSetAttribute(k_proj, cudaFuncAttributeMaxDynamicSharedMemorySize, P_TOTAL);
    k_proj<<<MTOT / 128, 256, P_TOTAL>>>(query);

    cudaFuncSetAttribute(k_attn, cudaFuncAttributeMaxDynamicSharedMemorySize, S_TOT);
    dim3 g3(LL / 128, BB);   // (16, 8) = 128 CTAs, one wave
    k_attn<<<g3, 256, S_TOT>>>(pid, out);
}